// round 13
// baseline (speedup 1.0000x reference)
#include <cuda_runtime.h>
#include <cuda_bf16.h>
#include <cstdint>

#define BATCH 16384
#define HID   256
#define NROWS 1024
#define KP    768
#define KA    512
#define CROSS_OFF (16384*16*4)

// ---------------- persistent device state ----------------
__device__ __nv_bfloat16 g_Wp[4][NROWS*KP];            // split+permuted Whh
__device__ float         g_Wih[4][NROWS*4];            // permuted Wih
__device__ float         g_bias[4][NROWS];             // permuted bih+bhh
__device__ __nv_bfloat16 g_ApA[4][(size_t)BATCH*KA];   // split h, ping
__device__ __nv_bfloat16 g_ApB[4][(size_t)BATCH*KA];   // split h, pong
__device__ float         g_h[4][(size_t)BATCH*HID];
__device__ float         g_c[4][(size_t)BATCH*HID];
__device__ float         g_x[2][(size_t)BATCH*4];      // decoder feedback

// ---------------- helpers ----------------
__device__ __forceinline__ uint32_t su32(const void* p){
  return (uint32_t)__cvta_generic_to_shared(p);
}
__device__ __forceinline__ void cpa16(uint32_t d, const void* s){
  asm volatile("cp.async.cg.shared.global [%0],[%1],16;\n"::"r"(d),"l"(s):"memory");
}
__device__ __forceinline__ void ldm4(uint32_t* r, uint32_t a){
  asm volatile("ldmatrix.sync.aligned.m8n8.x4.shared.b16 {%0,%1,%2,%3},[%4];\n"
    :"=r"(r[0]),"=r"(r[1]),"=r"(r[2]),"=r"(r[3]):"r"(a));
}
__device__ __forceinline__ void mma_bf16(float* c, const uint32_t* a, uint32_t b0, uint32_t b1){
  asm volatile("mma.sync.aligned.m16n8k16.row.col.f32.bf16.bf16.f32 "
    "{%0,%1,%2,%3},{%4,%5,%6,%7},{%8,%9},{%0,%1,%2,%3};\n"
    :"+f"(c[0]),"+f"(c[1]),"+f"(c[2]),"+f"(c[3])
    :"r"(a[0]),"r"(a[1]),"r"(a[2]),"r"(a[3]),"r"(b0),"r"(b1));
}
__device__ __forceinline__ float sigf(float x){ return 1.f/(1.f+__expf(-x)); }

// ---------------- weight prep (permute rows to j=4n+g; bf16 hi/lo split) ----------------
__global__ void prep_k(const float* W0,const float* W1,const float* W2,const float* W3,
                       const float* I0,const float* I1,const float* I2,const float* I3,
                       const float* a0,const float* a1,const float* a2,const float* a3,
                       const float* h0,const float* h1,const float* h2,const float* h3){
  int gid = blockIdx.x*256 + threadIdx.x;      // 4*1024*256 threads
  int c = gid >> 18, j = (gid >> 8) & 1023, k = gid & 255;
  int n = j >> 2, g = j & 3, src = g*256 + n;
  const float* Wh = (c==0)?W0:(c==1)?W1:(c==2)?W2:W3;
  float w = Wh[src*256 + k];
  __nv_bfloat16 hi = __float2bfloat16(w);
  __nv_bfloat16 lo = __float2bfloat16(w - __bfloat162float(hi));
  __nv_bfloat16* wp = g_Wp[c] + (size_t)j*KP;
  wp[k] = hi; wp[256+k] = lo; wp[512+k] = hi;
  if (k < 4) {
    const float* Wi = (c==0)?I0:(c==1)?I1:(c==2)?I2:I3;
    g_Wih[c][j*4+k] = Wi[src*4+k];
  }
  if (k == 0) {
    const float* bi = (c==0)?a0:(c==1)?a1:(c==2)?a2:a3;
    const float* bh = (c==0)?h0:(c==1)?h1:(c==2)?h2:h3;
    g_bias[c][j] = bi[src] + bh[src];
  }
}

// zero initial h-split (cells 0,1) and c (cells 0,1)
__global__ void zero_k(){
  size_t i = (size_t)blockIdx.x*256 + threadIdx.x;     // 4194304 threads
  uint4 z = make_uint4(0,0,0,0);
  if (i < 2097152) ((uint4*)g_ApA[0])[i] = z;          // 2 cells * B*KA bf16
  else             ((uint4*)g_c[0])[i-2097152] = z;    // 2 cells * B*HID f32
}

// ---------------- fused GEMM + LSTM pointwise step ----------------
// grid: (8 Ntiles, 128 Mtiles, 2 cells), block 256
__global__ void __launch_bounds__(256,2) lstm_step(
    int cellBase, int pp, const float* xe0, const float* xe1, int xs, int wrH)
{
  int cell = cellBase + blockIdx.z;
  const __nv_bfloat16* Ain  = pp ? g_ApB[cell] : g_ApA[cell];
  __nv_bfloat16*       Aout = pp ? g_ApA[cell] : g_ApB[cell];
  const __nv_bfloat16* Wp   = g_Wp[cell];
  const float* xp = xe0 ? (blockIdx.z ? xe1 : xe0) : g_x[blockIdx.z];
  int m0 = blockIdx.y * 128;
  int n0 = blockIdx.x * 128;
  int tid = threadIdx.x, lane = tid & 31, wid = tid >> 5;
  int wm = wid & 3, wn = wid >> 2;

  __shared__ __align__(16) char smraw[40960];
  __shared__ float s_wih[512];
  __shared__ float s_b[128];
  __nv_bfloat16* sA = (__nv_bfloat16*)smraw;            // [2][128][40]
  __nv_bfloat16* sB = (__nv_bfloat16*)(smraw + 20480);  // [2][128][40]
  float*         sC = (float*)smraw;                    // [128][66] (aliased)

  s_wih[tid]     = g_Wih[cell][n0*4 + tid];
  s_wih[tid+256] = g_Wih[cell][n0*4 + 256 + tid];
  if (tid < 128) s_b[tid] = g_bias[cell][n0 + tid];

  int lrow = tid >> 1;
  int lseg = (tid & 1) * 16;   // bf16 element offset (0 or 16) within 32-wide row

  float acc[2][8][4];
  #pragma unroll
  for (int a=0;a<2;a++)
    #pragma unroll
    for (int b=0;b<8;b++)
      #pragma unroll
      for (int e=0;e<4;e++) acc[a][b][e] = 0.f;

  // prefetch kt=0 into buf 0
  {
    const __nv_bfloat16* sa = Ain + (size_t)(m0+lrow)*KA + 0 + lseg;
    uint32_t da = su32(sA + lrow*40 + lseg);
    cpa16(da, sa); cpa16(da+16, sa+8);
    const __nv_bfloat16* sb = Wp + (size_t)(n0+lrow)*KP + 0 + lseg;
    uint32_t db = su32(sB + lrow*40 + lseg);
    cpa16(db, sb); cpa16(db+16, sb+8);
  }
  asm volatile("cp.async.commit_group;\n":::"memory");

  int buf = 0;
  for (int kt = 0; kt < 24; ++kt) {
    if (kt+1 < 24) {
      int ktn = kt+1;
      int aoff = ((ktn & 7) << 5) + ((ktn >= 16) ? 256 : 0);
      const __nv_bfloat16* sa = Ain + (size_t)(m0+lrow)*KA + aoff + lseg;
      uint32_t da = su32(sA + (buf^1)*5120 + lrow*40 + lseg);
      cpa16(da, sa); cpa16(da+16, sa+8);
      const __nv_bfloat16* sb = Wp + (size_t)(n0+lrow)*KP + (ktn<<5) + lseg;
      uint32_t db = su32(sB + (buf^1)*5120 + lrow*40 + lseg);
      cpa16(db, sb); cpa16(db+16, sb+8);
    }
    asm volatile("cp.async.commit_group;\n":::"memory");
    asm volatile("cp.async.wait_group 1;\n":::"memory");
    __syncthreads();

    int q = lane >> 3, r = lane & 7;
    int rq = ((q & 1) << 3) + r;      // row offset within 16-row frag
    int cq = (q >> 1) << 4;           // byte offset (0/16) for k half
    #pragma unroll
    for (int k2 = 0; k2 < 2; ++k2) {
      uint32_t afr[2][4];
      #pragma unroll
      for (int mi = 0; mi < 2; ++mi) {
        uint32_t ad = su32(sA + buf*5120 + (wm*32 + mi*16 + rq)*40) + k2*32 + cq;
        ldm4(afr[mi], ad);
      }
      uint32_t bfr[8][2];
      #pragma unroll
      for (int np = 0; np < 4; ++np) {
        uint32_t t4[4];
        uint32_t bd = su32(sB + buf*5120 + (wn*64 + np*16 + rq)*40) + k2*32 + cq;
        ldm4(t4, bd);
        bfr[2*np][0]=t4[0]; bfr[2*np+1][0]=t4[1];
        bfr[2*np][1]=t4[2]; bfr[2*np+1][1]=t4[3];
      }
      #pragma unroll
      for (int mi=0;mi<2;mi++)
        #pragma unroll
        for (int ni=0;ni<8;ni++)
          mma_bf16(acc[mi][ni], afr[mi], bfr[ni][0], bfr[ni][1]);
    }
    __syncthreads();
    buf ^= 1;
  }

  // ---- epilogue: two N-halves staged through sC ----
  for (int p = 0; p < 2; ++p) {
    __syncthreads();
    if (wn == p) {
      #pragma unroll
      for (int mi=0;mi<2;mi++)
        #pragma unroll
        for (int ni=0;ni<8;ni++)
          #pragma unroll
          for (int e=0;e<4;e++) {
            int row = wm*32 + mi*16 + (lane>>2) + ((e>>1)<<3);
            int col = ni*8 + ((lane&3)<<1) + (e&1);
            sC[row*66 + col] = acc[mi][ni][e];
          }
    }
    __syncthreads();
    int nl = tid & 15;
    #pragma unroll
    for (int it = 0; it < 8; ++it) {
      int ml = (tid >> 4) + it*16;
      int mg = m0 + ml;
      int ng = blockIdx.x*32 + p*16 + nl;
      float xv0 = xp[(size_t)mg*xs+0], xv1 = xp[(size_t)mg*xs+1];
      float xv2 = xp[(size_t)mg*xs+2], xv3 = xp[(size_t)mg*xs+3];
      float pr[4];
      #pragma unroll
      for (int g = 0; g < 4; ++g) {
        int jl = p*64 + nl*4 + g;
        pr[g] = sC[ml*66 + nl*4 + g] + s_b[jl]
              + xv0*s_wih[jl*4+0] + xv1*s_wih[jl*4+1]
              + xv2*s_wih[jl*4+2] + xv3*s_wih[jl*4+3];
      }
      float ig = sigf(pr[0]), fg = sigf(pr[1]);
      float gg = tanhf(pr[2]), og = sigf(pr[3]);
      size_t ci = (size_t)mg*HID + ng;
      float cn = fg * g_c[cell][ci] + ig * gg;
      float hn = og * tanhf(cn);
      g_c[cell][ci] = cn;
      if (wrH) g_h[cell][ci] = hn;
      __nv_bfloat16 hi = __float2bfloat16(hn);
      __nv_bfloat16 lo = __float2bfloat16(hn - __bfloat162float(hi));
      Aout[(size_t)mg*KA + ng] = hi;
      Aout[(size_t)mg*KA + 256 + ng] = lo;
    }
  }
}

// ---------------- combine encoders -> decoder init ----------------
__global__ void combine_k(const float* speed, const float* pos){
  size_t i = (size_t)blockIdx.x*256 + threadIdx.x;   // B*HID threads
  float h0 = g_h[0][i] + g_h[1][i];
  float c0 = g_c[0][i] + g_c[1][i];
  g_c[2][i] = c0; g_c[3][i] = c0;
  int b = (int)(i >> 8), n = (int)(i & 255);
  __nv_bfloat16 hi = __float2bfloat16(h0);
  __nv_bfloat16 lo = __float2bfloat16(h0 - __bfloat162float(hi));
  g_ApA[2][(size_t)b*KA+n]=hi; g_ApA[2][(size_t)b*KA+256+n]=lo;
  g_ApA[3][(size_t)b*KA+n]=hi; g_ApA[3][(size_t)b*KA+256+n]=lo;
  if (n < 4) {
    g_x[0][b*4+n] = speed[b*64 + 60 + n];
    g_x[1][b*4+n] = pos[b*64 + 60 + n];
  }
}

// ---------------- decoder heads (warp per batch row) ----------------
__global__ void heads_k(const float* fsW, const float* fsB, const float* fcW, const float* fcB,
                        const float* emW, const float* emB, float* out, int t){
  int lane = threadIdx.x & 31, wid = threadIdx.x >> 5;
  int b = blockIdx.x*4 + wid;
  const float* h2 = g_h[2] + (size_t)b*256 + lane*8;
  const float* h3 = g_h[3] + (size_t)b*256 + lane*8;
  float v2[8], v3[8];
  #pragma unroll
  for (int i=0;i<8;i++){ v2[i]=h2[i]; v3[i]=h3[i]; }
  float d[10];
  #pragma unroll
  for (int o=0;o<4;o++){ float s=0.f;
    #pragma unroll
    for (int i=0;i<8;i++) s += fsW[o*256+lane*8+i]*v2[i];
    d[o]=s; }
  #pragma unroll
  for (int o=0;o<2;o++){ float s=0.f;
    #pragma unroll
    for (int i=0;i<8;i++) s += fcW[o*256+lane*8+i]*v3[i];
    d[4+o]=s; }
  #pragma unroll
  for (int o=0;o<4;o++){ float s=0.f;
    #pragma unroll
    for (int i=0;i<8;i++) s += emW[o*256+lane*8+i]*v3[i];
    d[6+o]=s; }
  #pragma unroll
  for (int j=0;j<10;j++)
    #pragma unroll
    for (int s=16;s;s>>=1) d[j] += __shfl_xor_sync(0xffffffffu, d[j], s);
  if (lane == 0) {
    #pragma unroll
    for (int o=0;o<4;o++){
      float v = fminf(fmaxf(d[o]+fsB[o], -100.f), 100.f);
      out[(size_t)b*64 + t*4 + o] = v;
      g_x[0][b*4+o] = v;
    }
    float l0 = fmaxf(d[4]+fcB[0], 0.f), l1 = fmaxf(d[5]+fcB[1], 0.f);
    float mx = fmaxf(l0,l1);
    float e0 = __expf(l0-mx), e1 = __expf(l1-mx);
    float inv = 1.f/(e0+e1);
    out[CROSS_OFF + (size_t)b*32 + t*2 + 0] = e0*inv;
    out[CROSS_OFF + (size_t)b*32 + t*2 + 1] = e1*inv;
    #pragma unroll
    for (int o=0;o<4;o++) g_x[1][b*4+o] = fmaxf(d[6+o]+emB[o], 0.f);
  }
}

// ---------------- launcher ----------------
extern "C" void kernel_launch(void* const* d_in, const int* in_sizes, int n_in,
                              void* d_out, int out_size) {
  const float* speed = (const float*)d_in[0];
  const float* pos   = (const float*)d_in[1];
  prep_k<<<4096,256>>>(
    (const float*)d_in[3],(const float*)d_in[7],(const float*)d_in[11],(const float*)d_in[15],
    (const float*)d_in[2],(const float*)d_in[6],(const float*)d_in[10],(const float*)d_in[14],
    (const float*)d_in[4],(const float*)d_in[8],(const float*)d_in[12],(const float*)d_in[16],
    (const float*)d_in[5],(const float*)d_in[9],(const float*)d_in[13],(const float*)d_in[17]);
  zero_k<<<16384,256>>>();
  dim3 grid(8,128,2), blk(256,1,1);
  for (int t = 0; t < 16; ++t)
    lstm_step<<<grid,blk>>>(0, t&1, speed + t*4, pos + t*4, 64, (t==15)?1:0);
  combine_k<<<16384,256>>>(speed, pos);
  float* out = (float*)d_out;
  for (int t = 0; t < 16; ++t) {
    lstm_step<<<grid,blk>>>(2, t&1, nullptr, nullptr, 4, 1);
    heads_k<<<4096,128>>>((const float*)d_in[18],(const float*)d_in[19],
                          (const float*)d_in[20],(const float*)d_in[21],
                          (const float*)d_in[22],(const float*)d_in[23], out, t);
  }
}

// round 14
// speedup vs baseline: 1.7728x; 1.7728x over previous
#include <cuda_runtime.h>
#include <cuda_fp16.h>
#include <cstdint>

#define BATCH 16384
#define HID   256
#define NROWS 1024
#define KP    256
#define KA    256
#define CROSS_OFF (16384*16*4)

// ---------------- persistent device state ----------------
__device__ __half g_Wp[4][NROWS*KP];            // permuted Whh (fp16)
__device__ float  g_Wih[4][NROWS*4];            // permuted Wih
__device__ float  g_bias[4][NROWS];             // permuted bih+bhh
__device__ __half g_ApA[4][(size_t)BATCH*KA];   // h (fp16), ping
__device__ __half g_ApB[4][(size_t)BATCH*KA];   // h (fp16), pong
__device__ float  g_h[4][(size_t)BATCH*HID];
__device__ float  g_c[4][(size_t)BATCH*HID];
__device__ float  g_x[2][(size_t)BATCH*4];      // decoder feedback

// ---------------- helpers ----------------
__device__ __forceinline__ uint32_t su32(const void* p){
  return (uint32_t)__cvta_generic_to_shared(p);
}
__device__ __forceinline__ void cpa16(uint32_t d, const void* s){
  asm volatile("cp.async.cg.shared.global [%0],[%1],16;\n"::"r"(d),"l"(s):"memory");
}
__device__ __forceinline__ void ldm4(uint32_t* r, uint32_t a){
  asm volatile("ldmatrix.sync.aligned.m8n8.x4.shared.b16 {%0,%1,%2,%3},[%4];\n"
    :"=r"(r[0]),"=r"(r[1]),"=r"(r[2]),"=r"(r[3]):"r"(a));
}
__device__ __forceinline__ void mma_f16(float* c, const uint32_t* a, uint32_t b0, uint32_t b1){
  asm volatile("mma.sync.aligned.m16n8k16.row.col.f32.f16.f16.f32 "
    "{%0,%1,%2,%3},{%4,%5,%6,%7},{%8,%9},{%0,%1,%2,%3};\n"
    :"+f"(c[0]),"+f"(c[1]),"+f"(c[2]),"+f"(c[3])
    :"r"(a[0]),"r"(a[1]),"r"(a[2]),"r"(a[3]),"r"(b0),"r"(b1));
}
__device__ __forceinline__ float sigf(float x){ return 1.f/(1.f+__expf(-x)); }

// ---------------- weight prep (permute rows to j=4n+g; fp16) ----------------
__global__ void prep_k(const float* W0,const float* W1,const float* W2,const float* W3,
                       const float* I0,const float* I1,const float* I2,const float* I3,
                       const float* a0,const float* a1,const float* a2,const float* a3,
                       const float* h0,const float* h1,const float* h2,const float* h3){
  int gid = blockIdx.x*256 + threadIdx.x;      // 4*1024*256 threads
  int c = gid >> 18, j = (gid >> 8) & 1023, k = gid & 255;
  int n = j >> 2, g = j & 3, src = g*256 + n;
  const float* Wh = (c==0)?W0:(c==1)?W1:(c==2)?W2:W3;
  g_Wp[c][(size_t)j*KP + k] = __float2half_rn(Wh[src*256 + k]);
  if (k < 4) {
    const float* Wi = (c==0)?I0:(c==1)?I1:(c==2)?I2:I3;
    g_Wih[c][j*4+k] = Wi[src*4+k];
  }
  if (k == 0) {
    const float* bi = (c==0)?a0:(c==1)?a1:(c==2)?a2:a3;
    const float* bh = (c==0)?h0:(c==1)?h1:(c==2)?h2:h3;
    g_bias[c][j] = bi[src] + bh[src];
  }
}

// zero initial h (cells 0,1) and c (cells 0,1)
__global__ void zero_k(){
  size_t i = (size_t)blockIdx.x*256 + threadIdx.x;     // 3145728 threads
  uint4 z = make_uint4(0,0,0,0);
  if (i < 1048576) ((uint4*)g_ApA[0])[i] = z;          // 2 cells * B*KA fp16 = 16MB
  else             ((uint4*)g_c[0])[i-1048576] = z;    // 2 cells * B*HID f32 = 32MB
}

// ---------------- fused GEMM + LSTM pointwise step ----------------
// grid: (8 Ntiles, 128 Mtiles, 2 cells), block 256
__global__ void __launch_bounds__(256,2) lstm_step(
    int cellBase, int pp, const float* xe0, const float* xe1, int xs, int wrH)
{
  int cell = cellBase + blockIdx.z;
  const __half* Ain  = pp ? g_ApB[cell] : g_ApA[cell];
  __half*       Aout = pp ? g_ApA[cell] : g_ApB[cell];
  const __half* Wp   = g_Wp[cell];
  const float* xp = xe0 ? (blockIdx.z ? xe1 : xe0) : g_x[blockIdx.z];
  int m0 = blockIdx.y * 128;
  int n0 = blockIdx.x * 128;
  int tid = threadIdx.x, lane = tid & 31, wid = tid >> 5;
  int wm = wid & 3, wn = wid >> 2;

  __shared__ __align__(16) char smraw[40960];
  __shared__ float s_wih[512];
  __shared__ float s_b[128];
  __half* sA = (__half*)smraw;            // [2][128][40]
  __half* sB = (__half*)(smraw + 20480);  // [2][128][40]
  float*  sC = (float*)smraw;             // [128][66] (aliased)

  s_wih[tid]     = g_Wih[cell][n0*4 + tid];
  s_wih[tid+256] = g_Wih[cell][n0*4 + 256 + tid];
  if (tid < 128) s_b[tid] = g_bias[cell][n0 + tid];

  int lrow = tid >> 1;
  int lseg = (tid & 1) * 16;   // fp16 element offset (0/16) within 32-wide row

  float acc[2][8][4];
  #pragma unroll
  for (int a=0;a<2;a++)
    #pragma unroll
    for (int b=0;b<8;b++)
      #pragma unroll
      for (int e=0;e<4;e++) acc[a][b][e] = 0.f;

  // prefetch kt=0 into buf 0
  {
    const __half* sa = Ain + (size_t)(m0+lrow)*KA + lseg;
    uint32_t da = su32(sA + lrow*40 + lseg);
    cpa16(da, sa); cpa16(da+16, sa+8);
    const __half* sb = Wp + (size_t)(n0+lrow)*KP + lseg;
    uint32_t db = su32(sB + lrow*40 + lseg);
    cpa16(db, sb); cpa16(db+16, sb+8);
  }
  asm volatile("cp.async.commit_group;\n":::"memory");

  int buf = 0;
  #pragma unroll
  for (int kt = 0; kt < 8; ++kt) {
    if (kt+1 < 8) {
      int koff = ((kt+1) << 5) + lseg;
      const __half* sa = Ain + (size_t)(m0+lrow)*KA + koff;
      uint32_t da = su32(sA + (buf^1)*5120 + lrow*40 + lseg);
      cpa16(da, sa); cpa16(da+16, sa+8);
      const __half* sb = Wp + (size_t)(n0+lrow)*KP + koff;
      uint32_t db = su32(sB + (buf^1)*5120 + lrow*40 + lseg);
      cpa16(db, sb); cpa16(db+16, sb+8);
    }
    asm volatile("cp.async.commit_group;\n":::"memory");
    asm volatile("cp.async.wait_group 1;\n":::"memory");
    __syncthreads();

    int q = lane >> 3, r = lane & 7;
    int rq = ((q & 1) << 3) + r;      // row offset within 16-row frag
    int cq = (q >> 1) << 4;           // byte offset (0/16) for k half
    #pragma unroll
    for (int k2 = 0; k2 < 2; ++k2) {
      uint32_t afr[2][4];
      #pragma unroll
      for (int mi = 0; mi < 2; ++mi) {
        uint32_t ad = su32(sA + buf*5120 + (wm*32 + mi*16 + rq)*40) + k2*32 + cq;
        ldm4(afr[mi], ad);
      }
      uint32_t bfr[8][2];
      #pragma unroll
      for (int np = 0; np < 4; ++np) {
        uint32_t t4[4];
        uint32_t bd = su32(sB + buf*5120 + (wn*64 + np*16 + rq)*40) + k2*32 + cq;
        ldm4(t4, bd);
        bfr[2*np][0]=t4[0]; bfr[2*np+1][0]=t4[1];
        bfr[2*np][1]=t4[2]; bfr[2*np+1][1]=t4[3];
      }
      #pragma unroll
      for (int mi=0;mi<2;mi++)
        #pragma unroll
        for (int ni=0;ni<8;ni++)
          mma_f16(acc[mi][ni], afr[mi], bfr[ni][0], bfr[ni][1]);
    }
    __syncthreads();
    buf ^= 1;
  }

  // ---- epilogue: two N-halves staged through sC ----
  for (int p = 0; p < 2; ++p) {
    __syncthreads();
    if (wn == p) {
      #pragma unroll
      for (int mi=0;mi<2;mi++)
        #pragma unroll
        for (int ni=0;ni<8;ni++)
          #pragma unroll
          for (int e=0;e<4;e++) {
            int row = wm*32 + mi*16 + (lane>>2) + ((e>>1)<<3);
            int col = ni*8 + ((lane&3)<<1) + (e&1);
            sC[row*66 + col] = acc[mi][ni][e];
          }
    }
    __syncthreads();
    int nl = tid & 15;
    #pragma unroll
    for (int it = 0; it < 8; ++it) {
      int ml = (tid >> 4) + it*16;
      int mg = m0 + ml;
      int ng = blockIdx.x*32 + p*16 + nl;
      float xv0 = xp[(size_t)mg*xs+0], xv1 = xp[(size_t)mg*xs+1];
      float xv2 = xp[(size_t)mg*xs+2], xv3 = xp[(size_t)mg*xs+3];
      float pr[4];
      #pragma unroll
      for (int g = 0; g < 4; ++g) {
        int jl = p*64 + nl*4 + g;
        pr[g] = sC[ml*66 + nl*4 + g] + s_b[jl]
              + xv0*s_wih[jl*4+0] + xv1*s_wih[jl*4+1]
              + xv2*s_wih[jl*4+2] + xv3*s_wih[jl*4+3];
      }
      float ig = sigf(pr[0]), fg = sigf(pr[1]);
      float gg = tanhf(pr[2]), og = sigf(pr[3]);
      size_t ci = (size_t)mg*HID + ng;
      float cn = fg * g_c[cell][ci] + ig * gg;
      float hn = og * tanhf(cn);
      g_c[cell][ci] = cn;
      if (wrH) g_h[cell][ci] = hn;
      Aout[(size_t)mg*KA + ng] = __float2half_rn(hn);
    }
  }
}

// ---------------- combine encoders -> decoder init ----------------
__global__ void combine_k(const float* speed, const float* pos){
  size_t i = (size_t)blockIdx.x*256 + threadIdx.x;   // B*HID threads
  float h0 = g_h[0][i] + g_h[1][i];
  float c0 = g_c[0][i] + g_c[1][i];
  g_c[2][i] = c0; g_c[3][i] = c0;
  int b = (int)(i >> 8), n = (int)(i & 255);
  __half hh = __float2half_rn(h0);
  g_ApA[2][(size_t)b*KA+n] = hh;
  g_ApA[3][(size_t)b*KA+n] = hh;
  if (n < 4) {
    g_x[0][b*4+n] = speed[b*64 + 60 + n];
    g_x[1][b*4+n] = pos[b*64 + 60 + n];
  }
}

// ---------------- decoder heads (warp per batch row) ----------------
__global__ void heads_k(const float* fsW, const float* fsB, const float* fcW, const float* fcB,
                        const float* emW, const float* emB, float* out, int t){
  int lane = threadIdx.x & 31, wid = threadIdx.x >> 5;
  int b = blockIdx.x*4 + wid;
  const float* h2 = g_h[2] + (size_t)b*256 + lane*8;
  const float* h3 = g_h[3] + (size_t)b*256 + lane*8;
  float v2[8], v3[8];
  #pragma unroll
  for (int i=0;i<8;i++){ v2[i]=h2[i]; v3[i]=h3[i]; }
  float d[10];
  #pragma unroll
  for (int o=0;o<4;o++){ float s=0.f;
    #pragma unroll
    for (int i=0;i<8;i++) s += fsW[o*256+lane*8+i]*v2[i];
    d[o]=s; }
  #pragma unroll
  for (int o=0;o<2;o++){ float s=0.f;
    #pragma unroll
    for (int i=0;i<8;i++) s += fcW[o*256+lane*8+i]*v3[i];
    d[4+o]=s; }
  #pragma unroll
  for (int o=0;o<4;o++){ float s=0.f;
    #pragma unroll
    for (int i=0;i<8;i++) s += emW[o*256+lane*8+i]*v3[i];
    d[6+o]=s; }
  #pragma unroll
  for (int j=0;j<10;j++)
    #pragma unroll
    for (int s=16;s;s>>=1) d[j] += __shfl_xor_sync(0xffffffffu, d[j], s);
  if (lane == 0) {
    #pragma unroll
    for (int o=0;o<4;o++){
      float v = fminf(fmaxf(d[o]+fsB[o], -100.f), 100.f);
      out[(size_t)b*64 + t*4 + o] = v;
      g_x[0][b*4+o] = v;
    }
    float l0 = fmaxf(d[4]+fcB[0], 0.f), l1 = fmaxf(d[5]+fcB[1], 0.f);
    float mx = fmaxf(l0,l1);
    float e0 = __expf(l0-mx), e1 = __expf(l1-mx);
    float inv = 1.f/(e0+e1);
    out[CROSS_OFF + (size_t)b*32 + t*2 + 0] = e0*inv;
    out[CROSS_OFF + (size_t)b*32 + t*2 + 1] = e1*inv;
    #pragma unroll
    for (int o=0;o<4;o++) g_x[1][b*4+o] = fmaxf(d[6+o]+emB[o], 0.f);
  }
}

// ---------------- launcher ----------------
extern "C" void kernel_launch(void* const* d_in, const int* in_sizes, int n_in,
                              void* d_out, int out_size) {
  const float* speed = (const float*)d_in[0];
  const float* pos   = (const float*)d_in[1];
  prep_k<<<4096,256>>>(
    (const float*)d_in[3],(const float*)d_in[7],(const float*)d_in[11],(const float*)d_in[15],
    (const float*)d_in[2],(const float*)d_in[6],(const float*)d_in[10],(const float*)d_in[14],
    (const float*)d_in[4],(const float*)d_in[8],(const float*)d_in[12],(const float*)d_in[16],
    (const float*)d_in[5],(const float*)d_in[9],(const float*)d_in[13],(const float*)d_in[17]);
  zero_k<<<12288,256>>>();
  dim3 grid(8,128,2), blk(256,1,1);
  for (int t = 0; t < 16; ++t)
    lstm_step<<<grid,blk>>>(0, t&1, speed + t*4, pos + t*4, 64, (t==15)?1:0);
  combine_k<<<16384,256>>>(speed, pos);
  float* out = (float*)d_out;
  for (int t = 0; t < 16; ++t) {
    lstm_step<<<grid,blk>>>(2, t&1, nullptr, nullptr, 4, 1);
    heads_k<<<4096,128>>>((const float*)d_in[18],(const float*)d_in[19],
                          (const float*)d_in[20],(const float*)d_in[21],
                          (const float*)d_in[22],(const float*)d_in[23], out, t);
  }
}

// round 15
// speedup vs baseline: 1.7757x; 1.0016x over previous
#include <cuda_runtime.h>
#include <cuda_fp16.h>
#include <cstdint>

#define BATCH 16384
#define HID   256
#define NROWS 1024
#define KP    256
#define KA    256
#define CROSS_OFF (16384*16*4)

// ---------------- persistent device state ----------------
__device__ __half g_Wp[4][NROWS*KP];            // permuted Whh (fp16)
__device__ float  g_Wih[4][NROWS*4];            // permuted Wih
__device__ float  g_bias[4][NROWS];             // permuted bih+bhh
__device__ __half g_ApA[4][(size_t)BATCH*KA];   // h (fp16), ping
__device__ __half g_ApB[4][(size_t)BATCH*KA];   // h (fp16), pong
__device__ float  g_h[4][(size_t)BATCH*HID];
__device__ float  g_c[4][(size_t)BATCH*HID];
__device__ float  g_x[2][(size_t)BATCH*4];      // decoder feedback

// ---------------- helpers ----------------
__device__ __forceinline__ uint32_t su32(const void* p){
  return (uint32_t)__cvta_generic_to_shared(p);
}
__device__ __forceinline__ void cpa16(uint32_t d, const void* s){
  asm volatile("cp.async.cg.shared.global [%0],[%1],16;\n"::"r"(d),"l"(s):"memory");
}
__device__ __forceinline__ void ldm4(uint32_t* r, uint32_t a){
  asm volatile("ldmatrix.sync.aligned.m8n8.x4.shared.b16 {%0,%1,%2,%3},[%4];\n"
    :"=r"(r[0]),"=r"(r[1]),"=r"(r[2]),"=r"(r[3]):"r"(a));
}
__device__ __forceinline__ void mma_f16(float* c, const uint32_t* a, uint32_t b0, uint32_t b1){
  asm volatile("mma.sync.aligned.m16n8k16.row.col.f32.f16.f16.f32 "
    "{%0,%1,%2,%3},{%4,%5,%6,%7},{%8,%9},{%0,%1,%2,%3};\n"
    :"+f"(c[0]),"+f"(c[1]),"+f"(c[2]),"+f"(c[3])
    :"r"(a[0]),"r"(a[1]),"r"(a[2]),"r"(a[3]),"r"(b0),"r"(b1));
}
__device__ __forceinline__ float sigf(float x){ return 1.f/(1.f+__expf(-x)); }

// ---------------- weight prep (permute rows to j=4n+g; fp16) ----------------
__global__ void prep_k(const float* W0,const float* W1,const float* W2,const float* W3,
                       const float* I0,const float* I1,const float* I2,const float* I3,
                       const float* a0,const float* a1,const float* a2,const float* a3,
                       const float* h0,const float* h1,const float* h2,const float* h3){
  int gid = blockIdx.x*256 + threadIdx.x;      // 4*1024*256 threads
  int c = gid >> 18, j = (gid >> 8) & 1023, k = gid & 255;
  int n = j >> 2, g = j & 3, src = g*256 + n;
  const float* Wh = (c==0)?W0:(c==1)?W1:(c==2)?W2:W3;
  g_Wp[c][(size_t)j*KP + k] = __float2half_rn(Wh[src*256 + k]);
  if (k < 4) {
    const float* Wi = (c==0)?I0:(c==1)?I1:(c==2)?I2:I3;
    g_Wih[c][j*4+k] = Wi[src*4+k];
  }
  if (k == 0) {
    const float* bi = (c==0)?a0:(c==1)?a1:(c==2)?a2:a3;
    const float* bh = (c==0)?h0:(c==1)?h1:(c==2)?h2:h3;
    g_bias[c][j] = bi[src] + bh[src];
  }
}

// zero initial h (cells 0,1) and c (cells 0,1)
__global__ void zero_k(){
  size_t i = (size_t)blockIdx.x*256 + threadIdx.x;     // 3145728 threads
  uint4 z = make_uint4(0,0,0,0);
  if (i < 1048576) ((uint4*)g_ApA[0])[i] = z;          // 2 cells * B*KA fp16 = 16MB
  else             ((uint4*)g_c[0])[i-1048576] = z;    // 2 cells * B*HID f32 = 32MB
}

// ---------------- fused GEMM + LSTM pointwise step ----------------
// grid: (8 Ntiles, 128 Mtiles, 2 cells), block 256
__global__ void __launch_bounds__(256,2) lstm_step(
    int cellBase, int pp, const float* xe0, const float* xe1, int xs, int wrH)
{
  int cell = cellBase + blockIdx.z;
  const __half* Ain  = pp ? g_ApB[cell] : g_ApA[cell];
  __half*       Aout = pp ? g_ApA[cell] : g_ApB[cell];
  const __half* Wp   = g_Wp[cell];
  const float* xp = xe0 ? (blockIdx.z ? xe1 : xe0) : g_x[blockIdx.z];
  int m0 = blockIdx.y * 128;
  int n0 = blockIdx.x * 128;
  int tid = threadIdx.x, lane = tid & 31, wid = tid >> 5;
  int wm = wid & 3, wn = wid >> 2;

  __shared__ __align__(16) char smraw[40960];
  __shared__ float s_wih[512];
  __shared__ float s_b[128];
  __half* sA = (__half*)smraw;            // [2][128][40]
  __half* sB = (__half*)(smraw + 20480);  // [2][128][40]
  float*  sC = (float*)smraw;             // [128][66] (aliased)

  s_wih[tid]     = g_Wih[cell][n0*4 + tid];
  s_wih[tid+256] = g_Wih[cell][n0*4 + 256 + tid];
  if (tid < 128) s_b[tid] = g_bias[cell][n0 + tid];

  int lrow = tid >> 1;
  int lseg = (tid & 1) * 16;   // fp16 element offset (0/16) within 32-wide row

  float acc[2][8][4];
  #pragma unroll
  for (int a=0;a<2;a++)
    #pragma unroll
    for (int b=0;b<8;b++)
      #pragma unroll
      for (int e=0;e<4;e++) acc[a][b][e] = 0.f;

  // prefetch kt=0 into buf 0
  {
    const __half* sa = Ain + (size_t)(m0+lrow)*KA + lseg;
    uint32_t da = su32(sA + lrow*40 + lseg);
    cpa16(da, sa); cpa16(da+16, sa+8);
    const __half* sb = Wp + (size_t)(n0+lrow)*KP + lseg;
    uint32_t db = su32(sB + lrow*40 + lseg);
    cpa16(db, sb); cpa16(db+16, sb+8);
  }
  asm volatile("cp.async.commit_group;\n":::"memory");

  int buf = 0;
  #pragma unroll
  for (int kt = 0; kt < 8; ++kt) {
    if (kt+1 < 8) {
      int koff = ((kt+1) << 5) + lseg;
      const __half* sa = Ain + (size_t)(m0+lrow)*KA + koff;
      uint32_t da = su32(sA + (buf^1)*5120 + lrow*40 + lseg);
      cpa16(da, sa); cpa16(da+16, sa+8);
      const __half* sb = Wp + (size_t)(n0+lrow)*KP + koff;
      uint32_t db = su32(sB + (buf^1)*5120 + lrow*40 + lseg);
      cpa16(db, sb); cpa16(db+16, sb+8);
    }
    asm volatile("cp.async.commit_group;\n":::"memory");
    asm volatile("cp.async.wait_group 1;\n":::"memory");
    __syncthreads();

    int q = lane >> 3, r = lane & 7;
    int rq = ((q & 1) << 3) + r;      // row offset within 16-row frag
    int cq = (q >> 1) << 4;           // byte offset (0/16) for k half
    #pragma unroll
    for (int k2 = 0; k2 < 2; ++k2) {
      uint32_t afr[2][4];
      #pragma unroll
      for (int mi = 0; mi < 2; ++mi) {
        uint32_t ad = su32(sA + buf*5120 + (wm*32 + mi*16 + rq)*40) + k2*32 + cq;
        ldm4(afr[mi], ad);
      }
      uint32_t bfr[8][2];
      #pragma unroll
      for (int np = 0; np < 4; ++np) {
        uint32_t t4[4];
        uint32_t bd = su32(sB + buf*5120 + (wn*64 + np*16 + rq)*40) + k2*32 + cq;
        ldm4(t4, bd);
        bfr[2*np][0]=t4[0]; bfr[2*np+1][0]=t4[1];
        bfr[2*np][1]=t4[2]; bfr[2*np+1][1]=t4[3];
      }
      #pragma unroll
      for (int mi=0;mi<2;mi++)
        #pragma unroll
        for (int ni=0;ni<8;ni++)
          mma_f16(acc[mi][ni], afr[mi], bfr[ni][0], bfr[ni][1]);
    }
    __syncthreads();
    buf ^= 1;
  }

  // ---- epilogue: two N-halves staged through sC ----
  for (int p = 0; p < 2; ++p) {
    __syncthreads();
    if (wn == p) {
      #pragma unroll
      for (int mi=0;mi<2;mi++)
        #pragma unroll
        for (int ni=0;ni<8;ni++)
          #pragma unroll
          for (int e=0;e<4;e++) {
            int row = wm*32 + mi*16 + (lane>>2) + ((e>>1)<<3);
            int col = ni*8 + ((lane&3)<<1) + (e&1);
            sC[row*66 + col] = acc[mi][ni][e];
          }
    }
    __syncthreads();
    int nl = tid & 15;
    #pragma unroll
    for (int it = 0; it < 8; ++it) {
      int ml = (tid >> 4) + it*16;
      int mg = m0 + ml;
      int ng = blockIdx.x*32 + p*16 + nl;
      float xv0 = xp[(size_t)mg*xs+0], xv1 = xp[(size_t)mg*xs+1];
      float xv2 = xp[(size_t)mg*xs+2], xv3 = xp[(size_t)mg*xs+3];
      float pr[4];
      #pragma unroll
      for (int g = 0; g < 4; ++g) {
        int jl = p*64 + nl*4 + g;
        pr[g] = sC[ml*66 + nl*4 + g] + s_b[jl]
              + xv0*s_wih[jl*4+0] + xv1*s_wih[jl*4+1]
              + xv2*s_wih[jl*4+2] + xv3*s_wih[jl*4+3];
      }
      float ig = sigf(pr[0]), fg = sigf(pr[1]);
      float gg = tanhf(pr[2]), og = sigf(pr[3]);
      size_t ci = (size_t)mg*HID + ng;
      float cn = fg * g_c[cell][ci] + ig * gg;
      float hn = og * tanhf(cn);
      g_c[cell][ci] = cn;
      if (wrH) g_h[cell][ci] = hn;
      Aout[(size_t)mg*KA + ng] = __float2half_rn(hn);
    }
  }
}

// ---------------- combine encoders -> decoder init ----------------
__global__ void combine_k(const float* speed, const float* pos){
  size_t i = (size_t)blockIdx.x*256 + threadIdx.x;   // B*HID threads
  float h0 = g_h[0][i] + g_h[1][i];
  float c0 = g_c[0][i] + g_c[1][i];
  g_c[2][i] = c0; g_c[3][i] = c0;
  int b = (int)(i >> 8), n = (int)(i & 255);
  __half hh = __float2half_rn(h0);
  g_ApA[2][(size_t)b*KA+n] = hh;
  g_ApA[3][(size_t)b*KA+n] = hh;
  if (n < 4) {
    g_x[0][b*4+n] = speed[b*64 + 60 + n];
    g_x[1][b*4+n] = pos[b*64 + 60 + n];
  }
}

// ---------------- decoder heads (warp per batch row) ----------------
__global__ void heads_k(const float* fsW, const float* fsB, const float* fcW, const float* fcB,
                        const float* emW, const float* emB, float* out, int t){
  int lane = threadIdx.x & 31, wid = threadIdx.x >> 5;
  int b = blockIdx.x*4 + wid;
  const float* h2 = g_h[2] + (size_t)b*256 + lane*8;
  const float* h3 = g_h[3] + (size_t)b*256 + lane*8;
  float v2[8], v3[8];
  #pragma unroll
  for (int i=0;i<8;i++){ v2[i]=h2[i]; v3[i]=h3[i]; }
  float d[10];
  #pragma unroll
  for (int o=0;o<4;o++){ float s=0.f;
    #pragma unroll
    for (int i=0;i<8;i++) s += fsW[o*256+lane*8+i]*v2[i];
    d[o]=s; }
  #pragma unroll
  for (int o=0;o<2;o++){ float s=0.f;
    #pragma unroll
    for (int i=0;i<8;i++) s += fcW[o*256+lane*8+i]*v3[i];
    d[4+o]=s; }
  #pragma unroll
  for (int o=0;o<4;o++){ float s=0.f;
    #pragma unroll
    for (int i=0;i<8;i++) s += emW[o*256+lane*8+i]*v3[i];
    d[6+o]=s; }
  #pragma unroll
  for (int j=0;j<10;j++)
    #pragma unroll
    for (int s=16;s;s>>=1) d[j] += __shfl_xor_sync(0xffffffffu, d[j], s);
  if (lane == 0) {
    #pragma unroll
    for (int o=0;o<4;o++){
      float v = fminf(fmaxf(d[o]+fsB[o], -100.f), 100.f);
      out[(size_t)b*64 + t*4 + o] = v;
      g_x[0][b*4+o] = v;
    }
    float l0 = fmaxf(d[4]+fcB[0], 0.f), l1 = fmaxf(d[5]+fcB[1], 0.f);
    float mx = fmaxf(l0,l1);
    float e0 = __expf(l0-mx), e1 = __expf(l1-mx);
    float inv = 1.f/(e0+e1);
    out[CROSS_OFF + (size_t)b*32 + t*2 + 0] = e0*inv;
    out[CROSS_OFF + (size_t)b*32 + t*2 + 1] = e1*inv;
    #pragma unroll
    for (int o=0;o<4;o++) g_x[1][b*4+o] = fmaxf(d[6+o]+emB[o], 0.f);
  }
}

// ---------------- launcher ----------------
extern "C" void kernel_launch(void* const* d_in, const int* in_sizes, int n_in,
                              void* d_out, int out_size) {
  const float* speed = (const float*)d_in[0];
  const float* pos   = (const float*)d_in[1];
  prep_k<<<4096,256>>>(
    (const float*)d_in[3],(const float*)d_in[7],(const float*)d_in[11],(const float*)d_in[15],
    (const float*)d_in[2],(const float*)d_in[6],(const float*)d_in[10],(const float*)d_in[14],
    (const float*)d_in[4],(const float*)d_in[8],(const float*)d_in[12],(const float*)d_in[16],
    (const float*)d_in[5],(const float*)d_in[9],(const float*)d_in[13],(const float*)d_in[17]);
  zero_k<<<12288,256>>>();
  dim3 grid(8,128,2), blk(256,1,1);
  for (int t = 0; t < 16; ++t)
    lstm_step<<<grid,blk>>>(0, t&1, speed + t*4, pos + t*4, 64, (t==15)?1:0);
  combine_k<<<16384,256>>>(speed, pos);
  float* out = (float*)d_out;
  for (int t = 0; t < 16; ++t) {
    lstm_step<<<grid,blk>>>(2, t&1, nullptr, nullptr, 4, 1);
    heads_k<<<4096,128>>>((const float*)d_in[18],(const float*)d_in[19],
                          (const float*)d_in[20],(const float*)d_in[21],
                          (const float*)d_in[22],(const float*)d_in[23], out, t);
  }
}